// round 10
// baseline (speedup 1.0000x reference)
#include <cuda_runtime.h>
#include <math.h>

#define H 2048
#define FOURH 8192
#define NT 256

// Scratch: hidden outputs of layers 0,1 + full partial-gate arrays for all 3 layers
__device__ __align__(16) float g_h[2 * H];
__device__ __align__(16) float g_pg[3 * FOURH];
__device__ int g_ctr[3];   // completion counters (self-reset by last block)

__device__ __forceinline__ float sigmoidf_(float v) { return 1.0f / (1.0f + expf(-v)); }

__device__ __forceinline__ float warp_red(float v) {
    #pragma unroll
    for (int o = 16; o > 0; o >>= 1) v += __shfl_xor_sync(0xffffffffu, v, o);
    return v;
}
__device__ __forceinline__ float d4(float4 a, float4 b) {
    return a.x * b.x + a.y * b.y + a.z * b.z + a.w * b.w;
}

// 4 dot products over 4 CONSECUTIVE rows [R, R+4) of W — one contiguous 32 KB
// stream per block. All 8 W loads front-batched into distinct registers.
__device__ __forceinline__ void dot4rows(const float* __restrict__ W, int R,
                                         const float* __restrict__ h, float s[4]) {
    const int t = threadIdx.x;
    const float4* h4 = reinterpret_cast<const float4*>(h);
    const float4* base = reinterpret_cast<const float4*>(W) + (size_t)R * 512;

    float4 a0 = __ldcs(base + t);
    float4 a1 = __ldcs(base + 512 + t);
    float4 a2 = __ldcs(base + 1024 + t);
    float4 a3 = __ldcs(base + 1536 + t);
    float4 b0 = __ldcs(base + 256 + t);
    float4 b1 = __ldcs(base + 768 + t);
    float4 b2 = __ldcs(base + 1280 + t);
    float4 b3 = __ldcs(base + 1792 + t);
    float4 hv0 = h4[t];
    float4 hv1 = h4[t + NT];

    s[0] = d4(a0, hv0) + d4(b0, hv1);
    s[1] = d4(a1, hv0) + d4(b1, hv1);
    s[2] = d4(a2, hv0) + d4(b2, hv1);
    s[3] = d4(a3, hv0) + d4(b3, hv1);
}

__device__ __forceinline__ void reduce4(float s[4], float tot[4]) {
    __shared__ float sm[NT / 32][4];
    const int lane = threadIdx.x & 31;
    const int w = threadIdx.x >> 5;
    #pragma unroll
    for (int g = 0; g < 4; g++) s[g] = warp_red(s[g]);
    if (lane == 0) {
        #pragma unroll
        for (int g = 0; g < 4; g++) sm[w][g] = s[g];
    }
    __syncthreads();
    if (threadIdx.x == 0) {
        #pragma unroll
        for (int g = 0; g < 4; g++) {
            float v = 0.0f;
            #pragma unroll
            for (int ww = 0; ww < NT / 32; ww++) v += sm[ww][g];
            tot[g] = v;
        }
    }
}

// Stage 1: 6144 blocks. sect = b/2048 selects {Whh0,Whh1,Whh2}; R = 4*(b%2048)
// spans all 8192 rows of that matrix. Partial gates (+biases, +x*Wih0 for L0)
// go to g_pg[sect]. The LAST block to finish runs the layer-0 epilogue.
__global__ void __launch_bounds__(NT) k_stage1(
    const float* __restrict__ x,
    const float* __restrict__ hid,
    const float* __restrict__ cell,
    const float* __restrict__ Wih0,
    const float* __restrict__ Whh0,
    const float* __restrict__ bih0, const float* __restrict__ bhh0,
    const float* __restrict__ Whh1,
    const float* __restrict__ bih1, const float* __restrict__ bhh1,
    const float* __restrict__ Whh2,
    const float* __restrict__ bih2, const float* __restrict__ bhh2,
    float* __restrict__ out)
{
    const int b = blockIdx.x;
    const int t = threadIdx.x;
    const int sect = b >> 11;
    const int R = (b & 2047) << 2;

    const float* W = (sect == 0) ? Whh0 : ((sect == 1) ? Whh1 : Whh2);
    const float* h = hid + sect * H;

    float s[4];
    dot4rows(W, R, h, s);
    float tot[4];
    reduce4(s, tot);

    __shared__ int slast;
    if (t == 0) {
        const float* bi = (sect == 0) ? bih0 : ((sect == 1) ? bih1 : bih2);
        const float* bb = (sect == 0) ? bhh0 : ((sect == 1) ? bhh1 : bhh2);
        float* pg = g_pg + sect * FOURH;
        if (sect == 0) {
            const float xv = __ldg(x);
            #pragma unroll
            for (int i = 0; i < 4; i++) {
                int r = R + i;
                pg[r] = tot[i] + xv * __ldg(Wih0 + r) + __ldg(bi + r) + __ldg(bb + r);
            }
        } else {
            #pragma unroll
            for (int i = 0; i < 4; i++) {
                int r = R + i;
                pg[r] = tot[i] + __ldg(bi + r) + __ldg(bb + r);
            }
        }
        __threadfence();
        slast = (atomicAdd(&g_ctr[0], 1) == 3 * 2048 - 1);
    }
    __syncthreads();

    if (slast) {
        // layer-0 elementwise epilogue (all 256 threads, 8 j's each, coalesced)
        #pragma unroll
        for (int jj = 0; jj < 8; jj++) {
            int j = t + jj * NT;
            float gi = __ldcg(&g_pg[j]);
            float gf = __ldcg(&g_pg[H + j]);
            float gg = __ldcg(&g_pg[2 * H + j]);
            float go = __ldcg(&g_pg[3 * H + j]);
            float c2 = sigmoidf_(gf) * __ldg(cell + j) + sigmoidf_(gi) * tanhf(gg);
            float h2 = sigmoidf_(go) * tanhf(c2);
            g_h[j] = h2;
            out[1 + j] = h2;
            out[1 + 3 * H + j] = c2;
        }
        if (t == 0) g_ctr[0] = 0;   // reset for next graph replay
    }
}

// Finish layer (1 or 2): 2048 blocks, rows [4b, 4b+4) of Wih (contiguous 32 KB),
// accumulate into g_pg[layer]. Last block runs the layer epilogue; layer 2's
// last block also computes y = Wout.h2 + bout exactly.
__global__ void __launch_bounds__(NT) k_finish(
    const float* __restrict__ Wih,
    const float* __restrict__ cell,
    const float* __restrict__ Wout,
    const float* __restrict__ bout,
    int layer,
    float* __restrict__ out)
{
    const int b = blockIdx.x;
    const int t = threadIdx.x;
    const int R = b << 2;
    const float* h = g_h + (layer - 1) * H;   // L1 flushed per launch -> plain loads safe

    float s[4];
    dot4rows(Wih, R, h, s);
    float tot[4];
    reduce4(s, tot);

    float* pg = g_pg + layer * FOURH;
    __shared__ int slast;
    __shared__ float sy[NT / 32];
    if (t == 0) {
        #pragma unroll
        for (int i = 0; i < 4; i++) {
            int r = R + i;
            pg[r] = pg[r] + tot[i];
        }
        __threadfence();
        slast = (atomicAdd(&g_ctr[layer], 1) == 2048 - 1);
    }
    __syncthreads();

    if (slast) {
        float yacc = 0.0f;
        #pragma unroll
        for (int jj = 0; jj < 8; jj++) {
            int j = t + jj * NT;
            float gi = __ldcg(&pg[j]);
            float gf = __ldcg(&pg[H + j]);
            float gg = __ldcg(&pg[2 * H + j]);
            float go = __ldcg(&pg[3 * H + j]);
            float c2 = sigmoidf_(gf) * __ldg(cell + layer * H + j)
                     + sigmoidf_(gi) * tanhf(gg);
            float h2 = sigmoidf_(go) * tanhf(c2);
            out[1 + layer * H + j] = h2;
            out[1 + 3 * H + layer * H + j] = c2;
            if (layer == 1) g_h[H + j] = h2;
            else            yacc += h2 * __ldg(Wout + j);
        }
        if (layer == 2) {
            const int lane = t & 31, w = t >> 5;
            yacc = warp_red(yacc);
            if (lane == 0) sy[w] = yacc;
            __syncthreads();
            if (t == 0) {
                float y = 0.0f;
                #pragma unroll
                for (int ww = 0; ww < NT / 32; ww++) y += sy[ww];
                out[0] = y + __ldg(bout);
            }
        }
        if (t == 0) g_ctr[layer] = 0;   // reset for next graph replay
    }
}

extern "C" void kernel_launch(void* const* d_in, const int* in_sizes, int n_in,
                              void* d_out, int out_size) {
    const float* x    = (const float*)d_in[0];
    const float* hid  = (const float*)d_in[1];
    const float* cell = (const float*)d_in[2];
    const float* Wih0 = (const float*)d_in[3];
    const float* Whh0 = (const float*)d_in[4];
    const float* bih0 = (const float*)d_in[5];
    const float* bhh0 = (const float*)d_in[6];
    const float* Wih1 = (const float*)d_in[7];
    const float* Whh1 = (const float*)d_in[8];
    const float* bih1 = (const float*)d_in[9];
    const float* bhh1 = (const float*)d_in[10];
    const float* Wih2 = (const float*)d_in[11];
    const float* Whh2 = (const float*)d_in[12];
    const float* bih2 = (const float*)d_in[13];
    const float* bhh2 = (const float*)d_in[14];
    const float* Wout = (const float*)d_in[15];
    const float* bout = (const float*)d_in[16];
    float* out = (float*)d_out;

    k_stage1<<<3 * 2048, NT>>>(x, hid, cell, Wih0,
                               Whh0, bih0, bhh0,
                               Whh1, bih1, bhh1,
                               Whh2, bih2, bhh2, out);
    k_finish<<<2048, NT>>>(Wih1, cell, Wout, bout, 1, out);
    k_finish<<<2048, NT>>>(Wih2, cell, Wout, bout, 2, out);
}